// round 15
// baseline (speedup 1.0000x reference)
#include <cuda_runtime.h>
#include <cuda_fp16.h>
#include <mma.h>

using namespace nvcuda;

#define N_NODES 50000
#define N_EDGES 800000
#define SCAN_NB ((N_NODES + 255) / 256)   // 196 blocks

// ---- scratch (allocation-free: __device__ globals; zero at module load) ----
__device__ float  g_deg  [N_NODES];       // re-zeroed by scan3 each run
__device__ float  g_dinv [N_NODES];
__device__ int    g_cnt  [N_NODES];       // re-zeroed by scan1 each run
__device__ int    g_off  [N_NODES + 1];
__device__ int    g_bsum [SCAN_NB];
__device__ int    g_rank [N_EDGES];       // within-bucket rank from hist
__device__ int2   g_edge [N_EDGES];       // (src_node, norm bits), CSR order
__device__ __half g_t  [N_NODES * 64];    // neighbor transform, fp16 storage
__device__ float  g_h  [N_NODES * 64];
__device__ float  g_h2 [N_NODES * 64];
// fp16 weight copies (converted once per launch)
__device__ __half g_Wa1h[64 * 64];
__device__ __half g_Wb1h[64 * 64];
__device__ __half g_Wa2h[64 * 64];
__device__ __half g_Wb2h[64 * 64];

// ---------------------------------------------------------------------------
// hist also captures each edge's within-bucket rank (the atomic's return).
__global__ void hist_kernel(const int* __restrict__ row, const int* __restrict__ col) {
    int e = blockIdx.x * blockDim.x + threadIdx.x;
    if (e < N_EDGES) {
        atomicAdd(&g_deg[row[e]], 1.0f);
        g_rank[e] = atomicAdd(&g_cnt[col[e]], 1);
    }
}

// ---------------------------------------------------------------------------
__device__ __forceinline__ int block_excl_scan_256(int v, int tid) {
    int lane = tid & 31, wid = tid >> 5;
    int x = v;
#pragma unroll
    for (int d = 1; d < 32; d <<= 1) {
        int y = __shfl_up_sync(0xFFFFFFFFu, x, d);
        if (lane >= d) x += y;
    }
    __shared__ int wsum[8];
    if (lane == 31) wsum[wid] = x;
    __syncthreads();
    if (wid == 0) {
        int w = (lane < 8) ? wsum[lane] : 0;
#pragma unroll
        for (int d = 1; d < 8; d <<= 1) {
            int y = __shfl_up_sync(0xFFFFFFFFu, w, d);
            if (lane >= d) w += y;
        }
        if (lane < 8) wsum[lane] = w;
    }
    __syncthreads();
    int incl = x + (wid > 0 ? wsum[wid - 1] : 0);
    return incl - v;
}

__global__ void scan1_kernel() {
    int i = blockIdx.x * 256 + threadIdx.x;
    int v = 0;
    if (i < N_NODES) {
        v = g_cnt[i];
        g_cnt[i] = 0;                        // self-clear for next replay
    }
    int excl = block_excl_scan_256(v, threadIdx.x);
    if (i < N_NODES) g_off[i] = excl;
    if (threadIdx.x == 255) g_bsum[blockIdx.x] = excl + v;
}

// merged scan2+scan3: each block redundantly scans the 196 block sums,
// then finalizes offsets, dinv, and re-zeros g_deg.
__global__ void scan3_kernel() {
    __shared__ int s_pref;
    int tid = threadIdx.x;
    int bs = (tid < SCAN_NB) ? g_bsum[tid] : 0;
    int excl = block_excl_scan_256(bs, tid);
    __shared__ int s_excl[256];
    s_excl[tid] = excl;
    __syncthreads();
    if (tid == 0) s_pref = s_excl[blockIdx.x];
    __syncthreads();

    int i = blockIdx.x * 256 + tid;
    if (i < N_NODES) {
        g_off[i] += s_pref;
        float d = g_deg[i];
        g_deg[i] = 0.0f;                     // self-clear for next replay
        g_dinv[i] = (d > 0.0f) ? rsqrtf(d) : 0.0f;
    }
    if (i == 0) g_off[N_NODES] = N_EDGES;
}

// atomic-free CSR build: position = off[col] + rank (rank captured in hist)
__global__ void build_kernel(const int* __restrict__ row, const int* __restrict__ col) {
    int e = blockIdx.x * blockDim.x + threadIdx.x;
    if (e < N_EDGES) {
        int r = row[e], c = col[e];
        int p = g_off[c] + g_rank[e];
        float nv = g_dinv[r] * g_dinv[c];
        g_edge[p] = make_int2(r, __float_as_int(nv));
    }
}

// ---------------------------------------------------------------------------
// Convert the four 64x64 layer weights to fp16 (runs every launch; cheap).
__global__ void convert_weights_kernel(const float* __restrict__ Wa1,
                                       const float* __restrict__ Wb1,
                                       const float* __restrict__ Wa2,
                                       const float* __restrict__ Wb2) {
    int i = blockIdx.x * blockDim.x + threadIdx.x;
    if (i < 64 * 64) {
        g_Wa1h[i] = __float2half(Wa1[i]);
        g_Wb1h[i] = __float2half(Wb1[i]);
        g_Wa2h[i] = __float2half(Wa2[i]);
        g_Wb2h[i] = __float2half(Wb2[i]);
    }
}

// ---------------------------------------------------------------------------
// Tensor-core dual GEMM (wmma fp16 in, fp32 accumulate):
//   T(fp16) = A @ Wa,  H(fp32) = A @ Wb + bias     A:[N,64], W:[64,64]
__global__ void dual_gemm_wmma(const float* __restrict__ A,
                               const __half* __restrict__ Wah,
                               const __half* __restrict__ Wbh,
                               const float* __restrict__ bias,
                               __half* __restrict__ T,
                               float* __restrict__ H) {
    __shared__ __half As[64][80];          // fp16 A tile, padded ld=80
    __shared__ float  stage[64][128];      // cols 0-63: T, 64-127: H

    const int tid  = threadIdx.x;
    const int row0 = blockIdx.x * 64;

    // load + convert A tile to fp16
    for (int i = tid; i < 64 * 16; i += 256) {
        int r = i >> 4, c4 = i & 15;
        float4 v = make_float4(0.f, 0.f, 0.f, 0.f);
        int gr = row0 + r;
        if (gr < N_NODES) v = __ldg(reinterpret_cast<const float4*>(A) + gr * 16 + c4);
        __half2 h01 = __floats2half2_rn(v.x, v.y);
        __half2 h23 = __floats2half2_rn(v.z, v.w);
        *reinterpret_cast<__half2*>(&As[r][c4 * 4 + 0]) = h01;
        *reinterpret_cast<__half2*>(&As[r][c4 * 4 + 2]) = h23;
    }
    __syncthreads();

    const int warp = tid >> 5;
    const int rt   = warp >> 1;            // row tile 0..3
    const int sel  = warp & 1;             // 0 -> T/Wa, 1 -> H/Wb
    const __half* W = sel ? Wbh : Wah;

    wmma::fragment<wmma::accumulator, 16, 16, 16, float> c[4];
#pragma unroll
    for (int nt = 0; nt < 4; nt++) wmma::fill_fragment(c[nt], 0.0f);

#pragma unroll
    for (int kc = 0; kc < 4; kc++) {
        wmma::fragment<wmma::matrix_a, 16, 16, 16, __half, wmma::row_major> a;
        wmma::load_matrix_sync(a, &As[rt * 16][kc * 16], 80);
#pragma unroll
        for (int nt = 0; nt < 4; nt++) {
            wmma::fragment<wmma::matrix_b, 16, 16, 16, __half, wmma::row_major> b;
            wmma::load_matrix_sync(b, W + (kc * 16) * 64 + nt * 16, 64);
            wmma::mma_sync(c[nt], a, b, c[nt]);
        }
    }

#pragma unroll
    for (int nt = 0; nt < 4; nt++)
        wmma::store_matrix_sync(&stage[rt * 16][sel * 64 + nt * 16], c[nt],
                                128, wmma::mem_row_major);
    __syncthreads();

    // epilogue: T -> fp16 (no bias), H -> fp32 + bias
    for (int i = tid; i < 64 * 16; i += 256) {
        int r = i >> 4, c4 = i & 15;
        int gr = row0 + r;
        if (gr < N_NODES) {
            float4 tv = *reinterpret_cast<float4*>(&stage[r][c4 * 4]);
            __half2 t01 = __floats2half2_rn(tv.x, tv.y);
            __half2 t23 = __floats2half2_rn(tv.z, tv.w);
            uint2 tp;
            tp.x = *reinterpret_cast<unsigned*>(&t01);
            tp.y = *reinterpret_cast<unsigned*>(&t23);
            *reinterpret_cast<uint2*>(reinterpret_cast<char*>(T) + (gr * 64 + c4 * 4) * 2) = tp;

            float4 hv = *reinterpret_cast<float4*>(&stage[r][64 + c4 * 4]);
            float4 bv = __ldg(reinterpret_cast<const float4*>(bias) + c4);
            hv.x += bv.x; hv.y += bv.y; hv.z += bv.z; hv.w += bv.w;
            *reinterpret_cast<float4*>(H + gr * 64 + c4 * 4) = hv;
        }
    }
}

// Output GEMM: C[N,32] = A[N,64] @ W[64,32] + b. fp32 FFMA, 128 threads.
__global__ void out_gemm_kernel(const float* __restrict__ A,
                                const float* __restrict__ W,
                                const float* __restrict__ bias,
                                float* __restrict__ C) {
    __shared__ float xs[64][65];
    const int tid  = threadIdx.x;
    const int row0 = blockIdx.x * 64;

    for (int i = tid; i < 64 * 16; i += 128) {
        int r = i >> 4, c4 = i & 15;
        float4 v = make_float4(0.f, 0.f, 0.f, 0.f);
        int gr = row0 + r;
        if (gr < N_NODES) v = __ldg(reinterpret_cast<const float4*>(A) + gr * 16 + c4);
        xs[r][c4 * 4 + 0] = v.x; xs[r][c4 * 4 + 1] = v.y;
        xs[r][c4 * 4 + 2] = v.z; xs[r][c4 * 4 + 3] = v.w;
    }
    __syncthreads();

    const int tr = tid >> 3, tc = tid & 7;
    const int r0 = tr * 4, c0 = tc * 4;

    float acc[4][4];
#pragma unroll
    for (int i = 0; i < 4; i++)
#pragma unroll
        for (int j = 0; j < 4; j++) acc[i][j] = 0.f;

#pragma unroll 8
    for (int k = 0; k < 64; k++) {
        float4 wv = __ldg(reinterpret_cast<const float4*>(W + k * 32 + c0));
        float x0 = xs[r0 + 0][k];
        float x1 = xs[r0 + 1][k];
        float x2 = xs[r0 + 2][k];
        float x3 = xs[r0 + 3][k];
        acc[0][0] = fmaf(x0, wv.x, acc[0][0]); acc[0][1] = fmaf(x0, wv.y, acc[0][1]);
        acc[0][2] = fmaf(x0, wv.z, acc[0][2]); acc[0][3] = fmaf(x0, wv.w, acc[0][3]);
        acc[1][0] = fmaf(x1, wv.x, acc[1][0]); acc[1][1] = fmaf(x1, wv.y, acc[1][1]);
        acc[1][2] = fmaf(x1, wv.z, acc[1][2]); acc[1][3] = fmaf(x1, wv.w, acc[1][3]);
        acc[2][0] = fmaf(x2, wv.x, acc[2][0]); acc[2][1] = fmaf(x2, wv.y, acc[2][1]);
        acc[2][2] = fmaf(x2, wv.z, acc[2][2]); acc[2][3] = fmaf(x2, wv.w, acc[2][3]);
        acc[3][0] = fmaf(x3, wv.x, acc[3][0]); acc[3][1] = fmaf(x3, wv.y, acc[3][1]);
        acc[3][2] = fmaf(x3, wv.z, acc[3][2]); acc[3][3] = fmaf(x3, wv.w, acc[3][3]);
    }

    float4 bv = __ldg(reinterpret_cast<const float4*>(bias + c0));
#pragma unroll
    for (int i = 0; i < 4; i++) {
        int gr = row0 + r0 + i;
        if (gr < N_NODES) {
            float4 o = make_float4(acc[i][0] + bv.x, acc[i][1] + bv.y,
                                   acc[i][2] + bv.z, acc[i][3] + bv.w);
            *reinterpret_cast<float4*>(C + gr * 32 + c0) = o;
        }
    }
}

// ---------------------------------------------------------------------------
// CSR aggregation + ReLU: 16 threads per node, fp16 t gather (8B/edge/thread),
// single int2 metadata load per edge.
__global__ void agg_kernel(const __half* __restrict__ t, float* __restrict__ h) {
    int gid  = blockIdx.x * blockDim.x + threadIdx.x;
    int node = gid >> 4;
    if (node >= N_NODES) return;
    int c4 = gid & 15;

    int s = g_off[node];
    int e = g_off[node + 1];

    float4 acc = *reinterpret_cast<const float4*>(h + node * 64 + c4 * 4);

    const char* tb = reinterpret_cast<const char*>(t);
    int cofs = c4 * 8;

    for (int j = s; j < e; j++) {
        int2  er = __ldg(&g_edge[j]);
        float nv = __int_as_float(er.y);
        uint2 hp = __ldg(reinterpret_cast<const uint2*>(tb + er.x * 128 + cofs));
        float2 v01 = __half22float2(*reinterpret_cast<__half2*>(&hp.x));
        float2 v23 = __half22float2(*reinterpret_cast<__half2*>(&hp.y));
        acc.x = fmaf(v01.x, nv, acc.x);
        acc.y = fmaf(v01.y, nv, acc.y);
        acc.z = fmaf(v23.x, nv, acc.z);
        acc.w = fmaf(v23.y, nv, acc.w);
    }

    acc.x = fmaxf(acc.x, 0.f);
    acc.y = fmaxf(acc.y, 0.f);
    acc.z = fmaxf(acc.z, 0.f);
    acc.w = fmaxf(acc.w, 0.f);
    *reinterpret_cast<float4*>(h + node * 64 + c4 * 4) = acc;
}

// ---------------------------------------------------------------------------
extern "C" void kernel_launch(void* const* d_in, const int* in_sizes, int n_in,
                              void* d_out, int out_size) {
    const float* x      = (const float*)d_in[0];
    const int*   ei     = (const int*)d_in[1];
    const int*   row    = ei;
    const int*   col    = ei + N_EDGES;
    const float* W_in1  = (const float*)d_in[2];
    const float* W_nb1  = (const float*)d_in[3];
    const float* b1     = (const float*)d_in[4];
    const float* W_in2  = (const float*)d_in[5];
    const float* W_nb2  = (const float*)d_in[6];
    const float* b2     = (const float*)d_in[7];
    const float* W_out  = (const float*)d_in[8];
    const float* b_out  = (const float*)d_in[9];
    float*       out    = (float*)d_out;

    __half *t_p, *wa1_p, *wb1_p, *wa2_p, *wb2_p;
    float *h_p, *h2_p;
    cudaGetSymbolAddress((void**)&t_p,   g_t);
    cudaGetSymbolAddress((void**)&h_p,   g_h);
    cudaGetSymbolAddress((void**)&h2_p,  g_h2);
    cudaGetSymbolAddress((void**)&wa1_p, g_Wa1h);
    cudaGetSymbolAddress((void**)&wb1_p, g_Wb1h);
    cudaGetSymbolAddress((void**)&wa2_p, g_Wa2h);
    cudaGetSymbolAddress((void**)&wb2_p, g_Wb2h);

    // lazy host-object init (first call is the uncaptured correctness run)
    static cudaStream_t s2 = nullptr;
    static cudaEvent_t  ev_fork = nullptr, ev_join = nullptr;
    if (!s2) {
        cudaStreamCreateWithFlags(&s2, cudaStreamNonBlocking);
        cudaEventCreateWithFlags(&ev_fork, cudaEventDisableTiming);
        cudaEventCreateWithFlags(&ev_join, cudaEventDisableTiming);
    }

    const int TB = 256;
    const int edge_blocks = (N_EDGES + TB - 1) / TB;
    const int gemm_blocks = (N_NODES + 63) / 64;
    const int agg_blocks  = (N_NODES * 16 + TB - 1) / TB;

    // fork: weight conversion + layer-1 dual GEMM on s2, concurrent with prolog
    cudaEventRecord(ev_fork, 0);
    cudaStreamWaitEvent(s2, ev_fork, 0);
    convert_weights_kernel<<<16, 256, 0, s2>>>(W_nb1, W_in1, W_nb2, W_in2);
    dual_gemm_wmma<<<gemm_blocks, 256, 0, s2>>>(x, wa1_p, wb1_p, b1, t_p, h_p);
    cudaEventRecord(ev_join, s2);

    // prolog on capture stream (atomic-free build via hist-captured ranks)
    hist_kernel<<<edge_blocks, TB>>>(row, col);
    scan1_kernel<<<SCAN_NB, 256>>>();
    scan3_kernel<<<SCAN_NB, 256>>>();
    build_kernel<<<edge_blocks, TB>>>(row, col);

    // join: agg1 needs both CSR and (t, h)
    cudaStreamWaitEvent(0, ev_join, 0);
    agg_kernel<<<agg_blocks, TB>>>(t_p, h_p);

    // layer 2 (tensor-core dual GEMM)
    dual_gemm_wmma<<<gemm_blocks, 256>>>(h_p, wa2_p, wb2_p, b2, t_p, h2_p);
    agg_kernel<<<agg_blocks, TB>>>(t_p, h2_p);

    // output projection (fp32)
    out_gemm_kernel<<<gemm_blocks, 128>>>(h2_p, W_out, b_out, out);
}

// round 16
// speedup vs baseline: 1.0635x; 1.0635x over previous
#include <cuda_runtime.h>
#include <cuda_fp16.h>
#include <mma.h>

using namespace nvcuda;

#define N_NODES 50000
#define N_EDGES 800000
#define FSCAN_NB 49                        // 49 blocks x 1024 = 50176 >= N_NODES

// ---- scratch (allocation-free: __device__ globals; zero at module load) ----
__device__ float  g_deg  [N_NODES];       // re-zeroed by scan each run
__device__ float  g_dinv [N_NODES];
__device__ int    g_cnt  [N_NODES];       // re-zeroed by scan each run
__device__ int    g_off  [N_NODES + 1];
__device__ int    g_cur  [N_NODES];
__device__ int    g_bsum [FSCAN_NB];
__device__ unsigned g_sync;               // monotonic grid-barrier counter
__device__ int2   g_edge [N_EDGES];       // (src_node, norm bits), CSR order
__device__ __half g_t  [N_NODES * 64];    // neighbor transform, fp16 storage
__device__ float  g_h  [N_NODES * 64];
__device__ float  g_h2 [N_NODES * 64];
// fp16 weight copies (converted once per launch)
__device__ __half g_Wa1h[64 * 64];
__device__ __half g_Wb1h[64 * 64];
__device__ __half g_Wa2h[64 * 64];
__device__ __half g_Wb2h[64 * 64];

// ---------------------------------------------------------------------------
__global__ void hist_kernel(const int* __restrict__ row, const int* __restrict__ col) {
    int e = blockIdx.x * blockDim.x + threadIdx.x;
    if (e < N_EDGES) {
        atomicAdd(&g_deg[row[e]], 1.0f);   // REDG (return unused)
        atomicAdd(&g_cnt[col[e]], 1);      // REDG (return unused)
    }
}

// ---------------------------------------------------------------------------
// Fused single-kernel scan: 49 blocks x 1024 threads, one grid barrier.
// Replaces scan1+scan3. All 49 blocks are co-resident (<< 148 SMs), so the
// monotonic-counter barrier cannot deadlock; no reset needed across replays.
__global__ void __launch_bounds__(1024, 1) scan_fused_kernel() {
    __shared__ int wsum[32];
    __shared__ int s_bs[FSCAN_NB];
    __shared__ int s_pref;

    const int tid = threadIdx.x;
    const int b   = blockIdx.x;
    const int i   = b * 1024 + tid;
    const int lane = tid & 31, wid = tid >> 5;

    int v = 0;
    if (i < N_NODES) {
        v = g_cnt[i];
        g_cnt[i] = 0;                      // self-clear for next replay
    }

    // block-wide exclusive scan (1024 threads = 32 warps)
    int x = v;
#pragma unroll
    for (int d = 1; d < 32; d <<= 1) {
        int y = __shfl_up_sync(0xFFFFFFFFu, x, d);
        if (lane >= d) x += y;
    }
    if (lane == 31) wsum[wid] = x;
    __syncthreads();
    if (wid == 0) {
        int w = wsum[lane];
#pragma unroll
        for (int d = 1; d < 32; d <<= 1) {
            int y = __shfl_up_sync(0xFFFFFFFFu, w, d);
            if (lane >= d) w += y;
        }
        wsum[lane] = w;
    }
    __syncthreads();
    int excl = x - v + (wid > 0 ? wsum[wid - 1] : 0);

    // publish block total, then grid barrier (monotonic counter)
    if (tid == 1023) g_bsum[b] = excl + v;
    __threadfence();
    __syncthreads();
    if (tid == 0) {
        unsigned ticket = atomicAdd(&g_sync, 1u);
        unsigned target = (ticket / FSCAN_NB + 1u) * FSCAN_NB;
        while (atomicOr(&g_sync, 0u) < target) { }
    }
    __syncthreads();

    // each block computes its prefix from the 49 block totals
    if (tid < FSCAN_NB) s_bs[tid] = g_bsum[tid];
    __syncthreads();
    if (tid == 0) {
        int run = 0;
        for (int j = 0; j < b; j++) run += s_bs[j];
        s_pref = run;
    }
    __syncthreads();

    // finalize offsets/cursors, dinv, deg clear
    if (i < N_NODES) {
        int o = excl + s_pref;
        g_off[i] = o;
        g_cur[i] = o;
        float d = g_deg[i];
        g_deg[i] = 0.0f;                   // self-clear for next replay
        g_dinv[i] = (d > 0.0f) ? rsqrtf(d) : 0.0f;
    }
    if (i == 0) g_off[N_NODES] = N_EDGES;
}

__global__ void build_kernel(const int* __restrict__ row, const int* __restrict__ col) {
    int e = blockIdx.x * blockDim.x + threadIdx.x;
    if (e < N_EDGES) {
        int r = row[e], c = col[e];
        int p = atomicAdd(&g_cur[c], 1);
        float nv = g_dinv[r] * g_dinv[c];
        g_edge[p] = make_int2(r, __float_as_int(nv));
    }
}

// ---------------------------------------------------------------------------
// Convert the four 64x64 layer weights to fp16 (runs every launch; cheap).
__global__ void convert_weights_kernel(const float* __restrict__ Wa1,
                                       const float* __restrict__ Wb1,
                                       const float* __restrict__ Wa2,
                                       const float* __restrict__ Wb2) {
    int i = blockIdx.x * blockDim.x + threadIdx.x;
    if (i < 64 * 64) {
        g_Wa1h[i] = __float2half(Wa1[i]);
        g_Wb1h[i] = __float2half(Wb1[i]);
        g_Wa2h[i] = __float2half(Wa2[i]);
        g_Wb2h[i] = __float2half(Wb2[i]);
    }
}

// ---------------------------------------------------------------------------
// Tensor-core dual GEMM (wmma fp16 in, fp32 accumulate):
//   T(fp16) = A @ Wa,  H(fp32) = A @ Wb + bias     A:[N,64], W:[64,64]
__global__ void dual_gemm_wmma(const float* __restrict__ A,
                               const __half* __restrict__ Wah,
                               const __half* __restrict__ Wbh,
                               const float* __restrict__ bias,
                               __half* __restrict__ T,
                               float* __restrict__ H) {
    __shared__ __half As[64][80];          // fp16 A tile, padded ld=80
    __shared__ float  stage[64][128];      // cols 0-63: T, 64-127: H

    const int tid  = threadIdx.x;
    const int row0 = blockIdx.x * 64;

    // load + convert A tile to fp16
    for (int i = tid; i < 64 * 16; i += 256) {
        int r = i >> 4, c4 = i & 15;
        float4 v = make_float4(0.f, 0.f, 0.f, 0.f);
        int gr = row0 + r;
        if (gr < N_NODES) v = __ldg(reinterpret_cast<const float4*>(A) + gr * 16 + c4);
        __half2 h01 = __floats2half2_rn(v.x, v.y);
        __half2 h23 = __floats2half2_rn(v.z, v.w);
        *reinterpret_cast<__half2*>(&As[r][c4 * 4 + 0]) = h01;
        *reinterpret_cast<__half2*>(&As[r][c4 * 4 + 2]) = h23;
    }
    __syncthreads();

    const int warp = tid >> 5;
    const int rt   = warp >> 1;            // row tile 0..3
    const int sel  = warp & 1;             // 0 -> T/Wa, 1 -> H/Wb
    const __half* W = sel ? Wbh : Wah;

    wmma::fragment<wmma::accumulator, 16, 16, 16, float> c[4];
#pragma unroll
    for (int nt = 0; nt < 4; nt++) wmma::fill_fragment(c[nt], 0.0f);

#pragma unroll
    for (int kc = 0; kc < 4; kc++) {
        wmma::fragment<wmma::matrix_a, 16, 16, 16, __half, wmma::row_major> a;
        wmma::load_matrix_sync(a, &As[rt * 16][kc * 16], 80);
#pragma unroll
        for (int nt = 0; nt < 4; nt++) {
            wmma::fragment<wmma::matrix_b, 16, 16, 16, __half, wmma::row_major> b;
            wmma::load_matrix_sync(b, W + (kc * 16) * 64 + nt * 16, 64);
            wmma::mma_sync(c[nt], a, b, c[nt]);
        }
    }

#pragma unroll
    for (int nt = 0; nt < 4; nt++)
        wmma::store_matrix_sync(&stage[rt * 16][sel * 64 + nt * 16], c[nt],
                                128, wmma::mem_row_major);
    __syncthreads();

    // epilogue: T -> fp16 (no bias), H -> fp32 + bias
    for (int i = tid; i < 64 * 16; i += 256) {
        int r = i >> 4, c4 = i & 15;
        int gr = row0 + r;
        if (gr < N_NODES) {
            float4 tv = *reinterpret_cast<float4*>(&stage[r][c4 * 4]);
            __half2 t01 = __floats2half2_rn(tv.x, tv.y);
            __half2 t23 = __floats2half2_rn(tv.z, tv.w);
            uint2 tp;
            tp.x = *reinterpret_cast<unsigned*>(&t01);
            tp.y = *reinterpret_cast<unsigned*>(&t23);
            *reinterpret_cast<uint2*>(reinterpret_cast<char*>(T) + (gr * 64 + c4 * 4) * 2) = tp;

            float4 hv = *reinterpret_cast<float4*>(&stage[r][64 + c4 * 4]);
            float4 bv = __ldg(reinterpret_cast<const float4*>(bias) + c4);
            hv.x += bv.x; hv.y += bv.y; hv.z += bv.z; hv.w += bv.w;
            *reinterpret_cast<float4*>(H + gr * 64 + c4 * 4) = hv;
        }
    }
}

// Output GEMM: C[N,32] = A[N,64] @ W[64,32] + b. fp32 FFMA, 128 threads.
__global__ void out_gemm_kernel(const float* __restrict__ A,
                                const float* __restrict__ W,
                                const float* __restrict__ bias,
                                float* __restrict__ C) {
    __shared__ float xs[64][65];
    const int tid  = threadIdx.x;
    const int row0 = blockIdx.x * 64;

    for (int i = tid; i < 64 * 16; i += 128) {
        int r = i >> 4, c4 = i & 15;
        float4 v = make_float4(0.f, 0.f, 0.f, 0.f);
        int gr = row0 + r;
        if (gr < N_NODES) v = __ldg(reinterpret_cast<const float4*>(A) + gr * 16 + c4);
        xs[r][c4 * 4 + 0] = v.x; xs[r][c4 * 4 + 1] = v.y;
        xs[r][c4 * 4 + 2] = v.z; xs[r][c4 * 4 + 3] = v.w;
    }
    __syncthreads();

    const int tr = tid >> 3, tc = tid & 7;
    const int r0 = tr * 4, c0 = tc * 4;

    float acc[4][4];
#pragma unroll
    for (int i = 0; i < 4; i++)
#pragma unroll
        for (int j = 0; j < 4; j++) acc[i][j] = 0.f;

#pragma unroll 8
    for (int k = 0; k < 64; k++) {
        float4 wv = __ldg(reinterpret_cast<const float4*>(W + k * 32 + c0));
        float x0 = xs[r0 + 0][k];
        float x1 = xs[r0 + 1][k];
        float x2 = xs[r0 + 2][k];
        float x3 = xs[r0 + 3][k];
        acc[0][0] = fmaf(x0, wv.x, acc[0][0]); acc[0][1] = fmaf(x0, wv.y, acc[0][1]);
        acc[0][2] = fmaf(x0, wv.z, acc[0][2]); acc[0][3] = fmaf(x0, wv.w, acc[0][3]);
        acc[1][0] = fmaf(x1, wv.x, acc[1][0]); acc[1][1] = fmaf(x1, wv.y, acc[1][1]);
        acc[1][2] = fmaf(x1, wv.z, acc[1][2]); acc[1][3] = fmaf(x1, wv.w, acc[1][3]);
        acc[2][0] = fmaf(x2, wv.x, acc[2][0]); acc[2][1] = fmaf(x2, wv.y, acc[2][1]);
        acc[2][2] = fmaf(x2, wv.z, acc[2][2]); acc[2][3] = fmaf(x2, wv.w, acc[2][3]);
        acc[3][0] = fmaf(x3, wv.x, acc[3][0]); acc[3][1] = fmaf(x3, wv.y, acc[3][1]);
        acc[3][2] = fmaf(x3, wv.z, acc[3][2]); acc[3][3] = fmaf(x3, wv.w, acc[3][3]);
    }

    float4 bv = __ldg(reinterpret_cast<const float4*>(bias + c0));
#pragma unroll
    for (int i = 0; i < 4; i++) {
        int gr = row0 + r0 + i;
        if (gr < N_NODES) {
            float4 o = make_float4(acc[i][0] + bv.x, acc[i][1] + bv.y,
                                   acc[i][2] + bv.z, acc[i][3] + bv.w);
            *reinterpret_cast<float4*>(C + gr * 32 + c0) = o;
        }
    }
}

// ---------------------------------------------------------------------------
// CSR aggregation + ReLU: 16 threads per node, fp16 t gather (8B/edge/thread),
// single int2 metadata load per edge.
__global__ void agg_kernel(const __half* __restrict__ t, float* __restrict__ h) {
    int gid  = blockIdx.x * blockDim.x + threadIdx.x;
    int node = gid >> 4;
    if (node >= N_NODES) return;
    int c4 = gid & 15;

    int s = g_off[node];
    int e = g_off[node + 1];

    float4 acc = *reinterpret_cast<const float4*>(h + node * 64 + c4 * 4);

    const char* tb = reinterpret_cast<const char*>(t);
    int cofs = c4 * 8;

    for (int j = s; j < e; j++) {
        int2  er = __ldg(&g_edge[j]);
        float nv = __int_as_float(er.y);
        uint2 hp = __ldg(reinterpret_cast<const uint2*>(tb + er.x * 128 + cofs));
        float2 v01 = __half22float2(*reinterpret_cast<__half2*>(&hp.x));
        float2 v23 = __half22float2(*reinterpret_cast<__half2*>(&hp.y));
        acc.x = fmaf(v01.x, nv, acc.x);
        acc.y = fmaf(v01.y, nv, acc.y);
        acc.z = fmaf(v23.x, nv, acc.z);
        acc.w = fmaf(v23.y, nv, acc.w);
    }

    acc.x = fmaxf(acc.x, 0.f);
    acc.y = fmaxf(acc.y, 0.f);
    acc.z = fmaxf(acc.z, 0.f);
    acc.w = fmaxf(acc.w, 0.f);
    *reinterpret_cast<float4*>(h + node * 64 + c4 * 4) = acc;
}

// ---------------------------------------------------------------------------
extern "C" void kernel_launch(void* const* d_in, const int* in_sizes, int n_in,
                              void* d_out, int out_size) {
    const float* x      = (const float*)d_in[0];
    const int*   ei     = (const int*)d_in[1];
    const int*   row    = ei;
    const int*   col    = ei + N_EDGES;
    const float* W_in1  = (const float*)d_in[2];
    const float* W_nb1  = (const float*)d_in[3];
    const float* b1     = (const float*)d_in[4];
    const float* W_in2  = (const float*)d_in[5];
    const float* W_nb2  = (const float*)d_in[6];
    const float* b2     = (const float*)d_in[7];
    const float* W_out  = (const float*)d_in[8];
    const float* b_out  = (const float*)d_in[9];
    float*       out    = (float*)d_out;

    __half *t_p, *wa1_p, *wb1_p, *wa2_p, *wb2_p;
    float *h_p, *h2_p;
    cudaGetSymbolAddress((void**)&t_p,   g_t);
    cudaGetSymbolAddress((void**)&h_p,   g_h);
    cudaGetSymbolAddress((void**)&h2_p,  g_h2);
    cudaGetSymbolAddress((void**)&wa1_p, g_Wa1h);
    cudaGetSymbolAddress((void**)&wb1_p, g_Wb1h);
    cudaGetSymbolAddress((void**)&wa2_p, g_Wa2h);
    cudaGetSymbolAddress((void**)&wb2_p, g_Wb2h);

    // lazy host-object init (first call is the uncaptured correctness run)
    static cudaStream_t s2 = nullptr;
    static cudaEvent_t  ev_fork = nullptr, ev_join = nullptr;
    if (!s2) {
        cudaStreamCreateWithFlags(&s2, cudaStreamNonBlocking);
        cudaEventCreateWithFlags(&ev_fork, cudaEventDisableTiming);
        cudaEventCreateWithFlags(&ev_join, cudaEventDisableTiming);
    }

    const int TB = 256;
    const int edge_blocks = (N_EDGES + TB - 1) / TB;
    const int gemm_blocks = (N_NODES + 63) / 64;
    const int agg_blocks  = (N_NODES * 16 + TB - 1) / TB;

    // fork: weight conversion + layer-1 dual GEMM on s2, concurrent with prolog
    cudaEventRecord(ev_fork, 0);
    cudaStreamWaitEvent(s2, ev_fork, 0);
    convert_weights_kernel<<<16, 256, 0, s2>>>(W_nb1, W_in1, W_nb2, W_in2);
    dual_gemm_wmma<<<gemm_blocks, 256, 0, s2>>>(x, wa1_p, wb1_p, b1, t_p, h_p);
    cudaEventRecord(ev_join, s2);

    // prolog on capture stream (fused single-kernel scan)
    hist_kernel<<<edge_blocks, TB>>>(row, col);
    scan_fused_kernel<<<FSCAN_NB, 1024>>>();
    build_kernel<<<edge_blocks, TB>>>(row, col);

    // join: agg1 needs both CSR and (t, h)
    cudaStreamWaitEvent(0, ev_join, 0);
    agg_kernel<<<agg_blocks, TB>>>(t_p, h_p);

    // layer 2 (tensor-core dual GEMM)
    dual_gemm_wmma<<<gemm_blocks, 256>>>(h_p, wa2_p, wb2_p, b2, t_p, h2_p);
    agg_kernel<<<agg_blocks, TB>>>(t_p, h2_p);

    // output projection (fp32)
    out_gemm_kernel<<<gemm_blocks, 128>>>(h2_p, W_out, b_out, out);
}